// round 16
// baseline (speedup 1.0000x reference)
#include <cuda_runtime.h>
#include <cuda_fp16.h>
#include <math.h>
#include <stdint.h>

// Problem constants
#define BB 2
#define TT 2048
#define CC 1024
#define NH 16
#define HD 64
#define MROWS (BB*TT)      // 4096
#define QKVN  (3*CC)       // 3072

// Scratch (allocation-free rule: __device__ globals)
__device__ __half g_xh[MROWS * CC];
__device__ __half g_wqkvh[CC * QKVN];
__device__ __half g_wouth[CC * CC];
__device__ __half g_qkv[MROWS * QKVN];
__device__ __half g_y[MROWS * CC];

// ---------------------------------------------------------------------------
// helpers
// ---------------------------------------------------------------------------
__device__ __forceinline__ void mma_f16(
    float& c0, float& c1, float& c2, float& c3,
    uint32_t a0, uint32_t a1, uint32_t a2, uint32_t a3,
    uint32_t b0, uint32_t b1)
{
    asm volatile(
        "mma.sync.aligned.m16n8k16.row.col.f32.f16.f16.f32 "
        "{%0,%1,%2,%3}, {%4,%5,%6,%7}, {%8,%9}, {%0,%1,%2,%3};"
        : "+f"(c0), "+f"(c1), "+f"(c2), "+f"(c3)
        : "r"(a0), "r"(a1), "r"(a2), "r"(a3), "r"(b0), "r"(b1));
}

__device__ __forceinline__ void ldsm_x4(
    uint32_t& r0, uint32_t& r1, uint32_t& r2, uint32_t& r3, uint32_t addr)
{
    asm volatile(
        "ldmatrix.sync.aligned.m8n8.x4.shared.b16 {%0,%1,%2,%3}, [%4];"
        : "=r"(r0), "=r"(r1), "=r"(r2), "=r"(r3) : "r"(addr));
}

__device__ __forceinline__ void ldsm_x4_trans(
    uint32_t& r0, uint32_t& r1, uint32_t& r2, uint32_t& r3, uint32_t addr)
{
    asm volatile(
        "ldmatrix.sync.aligned.m8n8.x4.trans.shared.b16 {%0,%1,%2,%3}, [%4];"
        : "=r"(r0), "=r"(r1), "=r"(r2), "=r"(r3) : "r"(addr));
}

__device__ __forceinline__ void cp_async16(uint32_t smem, const void* gmem) {
    asm volatile("cp.async.cg.shared.global [%0], [%1], 16;"
                 :: "r"(smem), "l"(gmem));
}
__device__ __forceinline__ void cp_commit() {
    asm volatile("cp.async.commit_group;");
}
template<int N>
__device__ __forceinline__ void cp_wait() {
    asm volatile("cp.async.wait_group %0;" :: "n"(N));
}

// ---------------------------------------------------------------------------
// fused fp32 -> fp16 conversion for three arrays in one launch
// ---------------------------------------------------------------------------
__global__ void f32_to_f16_fused(
    const float* __restrict__ in0, __half* __restrict__ out0, int n0,
    const float* __restrict__ in1, __half* __restrict__ out1, int n1,
    const float* __restrict__ in2, __half* __restrict__ out2, int n2)
{
    int i = (blockIdx.x * blockDim.x + threadIdx.x) * 8;
    const float* in; __half* out;
    if (i < n0)            { in = in0;            out = out0;            }
    else if (i < n0 + n1)  { in = in1 - n0;       out = out1 - n0;       }
    else if (i < n0+n1+n2) { in = in2 - n0 - n1;  out = out2 - n0 - n1;  }
    else return;
    float4 a = *(const float4*)&in[i];
    float4 b = *(const float4*)&in[i + 4];
    half2 h[4];
    h[0] = __floats2half2_rn(a.x, a.y);
    h[1] = __floats2half2_rn(a.z, a.w);
    h[2] = __floats2half2_rn(b.x, b.y);
    h[3] = __floats2half2_rn(b.z, b.w);
    *(uint4*)&out[i] = *(uint4*)&h[0];
}

// ---------------------------------------------------------------------------
// GEMM variant A (persistent, high-occupancy, for QKV): CTA 128x64 tiles,
// 8 warps (4m x 2n), warp tile 32x32, BK=32, 4-stage cp.async, 3 CTAs/SM.
// Persistent tile loop over (M/128)x(N/64) tiles -> no wave quantization.
// Scales Q columns (col < CC) by 1/8 in the epilogue.
// ---------------------------------------------------------------------------
#define HA_ASTRB 80
#define HA_BSTRB 144
#define HA_ABUF (128 * HA_ASTRB)
#define HA_BBUF (32 * HA_BSTRB)
#define HA_NSTG 4
#define HA_BBASE (HA_NSTG * HA_ABUF)
#define HA_SMEM (HA_NSTG * (HA_ABUF + HA_BBUF))   // 59392

__global__ void __launch_bounds__(256, 3) gemm_f16_qkv_persist(
    const __half* __restrict__ A, const __half* __restrict__ W,
    const float* __restrict__ bias, __half* __restrict__ out,
    int M, int N, int K)
{
    extern __shared__ __align__(16) char smem[];
    const uint32_t sb = (uint32_t)__cvta_generic_to_shared(smem);

    const int tid  = threadIdx.x;
    const int warp = tid >> 5;
    const int lane = tid & 31;
    const int g    = lane >> 2;
    const int tg   = lane & 3;

    const int wm = (warp & 3) * 32;
    const int wn = (warp >> 2) * 32;

    const int arow = tid >> 1, acol = (tid & 1) * 16;
    const int brow = tid >> 3, bcol = (tid & 7) * 8;

    const int NI = K / 32;
    const int TILES_N = N / 64;
    const int NTILES = (M / 128) * TILES_N;

    for (int tile = blockIdx.x; tile < NTILES; tile += gridDim.x) {
        const int m0 = (tile / TILES_N) * 128;
        const int n0 = (tile % TILES_N) * 64;

        float acc[2][4][4];
#pragma unroll
        for (int i = 0; i < 2; i++)
#pragma unroll
            for (int j = 0; j < 4; j++)
#pragma unroll
                for (int r = 0; r < 4; r++) acc[i][j][r] = 0.0f;

        auto issue = [&](int stage, int k0) {
            uint32_t sa = sb + stage * HA_ABUF + arow * HA_ASTRB + acol * 2;
            const __half* ga = &A[(size_t)(m0 + arow) * K + k0 + acol];
            cp_async16(sa,      ga);
            cp_async16(sa + 16, ga + 8);
            uint32_t sbuf = sb + HA_BBASE + stage * HA_BBUF + brow * HA_BSTRB + bcol * 2;
            const __half* gb = &W[(size_t)(k0 + brow) * N + n0 + bcol];
            cp_async16(sbuf, gb);
        };

#pragma unroll
        for (int s = 0; s < HA_NSTG - 1; s++) {
            if (s < NI) issue(s, s * 32);
            cp_commit();
        }

        for (int it = 0; it < NI; it++) {
            cp_wait<HA_NSTG - 2>();
            __syncthreads();

            int nxt = it + HA_NSTG - 1;
            if (nxt < NI) issue(nxt % HA_NSTG, nxt * 32);
            cp_commit();

            const int cur = it % HA_NSTG;
            const uint32_t abase = sb + cur * HA_ABUF;
            const uint32_t bbase = sb + HA_BBASE + cur * HA_BBUF;

#pragma unroll
            for (int kk = 0; kk < 32; kk += 16) {
                uint32_t af[2][4];
#pragma unroll
                for (int mt = 0; mt < 2; mt++) {
                    uint32_t addr = abase +
                        (wm + mt * 16 + (lane & 15)) * HA_ASTRB +
                        (kk + (lane >> 4) * 8) * 2;
                    ldsm_x4(af[mt][0], af[mt][1], af[mt][2], af[mt][3], addr);
                }
                uint32_t bf[4][2];
#pragma unroll
                for (int nt2 = 0; nt2 < 2; nt2++) {
                    uint32_t addr = bbase +
                        (kk + (lane & 15)) * HA_BSTRB +
                        (wn + nt2 * 16 + (lane >> 4) * 8) * 2;
                    uint32_t r0, r1, r2, r3;
                    ldsm_x4_trans(r0, r1, r2, r3, addr);
                    bf[nt2 * 2][0] = r0;     bf[nt2 * 2][1] = r1;
                    bf[nt2 * 2 + 1][0] = r2; bf[nt2 * 2 + 1][1] = r3;
                }
#pragma unroll
                for (int mt = 0; mt < 2; mt++)
#pragma unroll
                    for (int nt = 0; nt < 4; nt++)
                        mma_f16(acc[mt][nt][0], acc[mt][nt][1],
                                acc[mt][nt][2], acc[mt][nt][3],
                                af[mt][0], af[mt][1], af[mt][2], af[mt][3],
                                bf[nt][0], bf[nt][1]);
            }
        }

        // Epilogue: Q columns (col < CC) pre-scaled by 1/sqrt(HD) = 0.125
#pragma unroll
        for (int mt = 0; mt < 2; mt++) {
            int row = m0 + wm + mt * 16 + g;
#pragma unroll
            for (int nt = 0; nt < 4; nt++) {
                int col = n0 + wn + nt * 8 + tg * 2;
                float sc = (col < CC) ? 0.125f : 1.0f;
                float2 bv = *(const float2*)&bias[col];
                *(half2*)&out[(size_t)row * N + col] =
                    __floats2half2_rn((acc[mt][nt][0] + bv.x) * sc,
                                      (acc[mt][nt][1] + bv.y) * sc);
                *(half2*)&out[(size_t)(row + 8) * N + col] =
                    __floats2half2_rn((acc[mt][nt][2] + bv.x) * sc,
                                      (acc[mt][nt][3] + bv.y) * sc);
            }
        }

        __syncthreads();   // all warps done with smem before next tile refill
    }
}

// ---------------------------------------------------------------------------
// GEMM variant B (big tile, for out-proj, fp32 out): CTA 128x128, 8 warps
// (2m x 4n), warp tile 64x32, BK=32, 4-stage cp.async. (R12 shape)
// ---------------------------------------------------------------------------
#define BT_ASTRB 80
#define BT_BSTRB 272
#define BT_ABUF (128 * BT_ASTRB)
#define BT_BBUF (32 * BT_BSTRB)
#define BT_NSTG 4
#define BT_BBASE (BT_NSTG * BT_ABUF)
#define BT_SMEM (BT_NSTG * (BT_ABUF + BT_BBUF))   // 75776

__global__ void __launch_bounds__(256) gemm_f16_bt(
    const __half* __restrict__ A, const __half* __restrict__ W,
    const float* __restrict__ bias, float* __restrict__ out,
    int M, int N, int K)
{
    extern __shared__ __align__(16) char smem[];
    const uint32_t sb = (uint32_t)__cvta_generic_to_shared(smem);

    const int tid  = threadIdx.x;
    const int warp = tid >> 5;
    const int lane = tid & 31;
    const int g    = lane >> 2;
    const int tg   = lane & 3;

    const int wm = (warp & 1) * 64;
    const int wn = (warp >> 1) * 32;
    const int m0 = blockIdx.y * 128;
    const int n0 = blockIdx.x * 128;

    float acc[4][4][4];
#pragma unroll
    for (int i = 0; i < 4; i++)
#pragma unroll
        for (int j = 0; j < 4; j++)
#pragma unroll
            for (int r = 0; r < 4; r++) acc[i][j][r] = 0.0f;

    const int arow = tid >> 1, acol = (tid & 1) * 16;
    const int brow = tid >> 3, bcol = (tid & 7) * 16;

    const int NI = K / 32;

    auto issue = [&](int stage, int k0) {
        uint32_t sa = sb + stage * BT_ABUF + arow * BT_ASTRB + acol * 2;
        const __half* ga = &A[(size_t)(m0 + arow) * K + k0 + acol];
        cp_async16(sa,      ga);
        cp_async16(sa + 16, ga + 8);
        uint32_t sbuf = sb + BT_BBASE + stage * BT_BBUF + brow * BT_BSTRB + bcol * 2;
        const __half* gb = &W[(size_t)(k0 + brow) * N + n0 + bcol];
        cp_async16(sbuf,      gb);
        cp_async16(sbuf + 16, gb + 8);
    };

#pragma unroll
    for (int s = 0; s < BT_NSTG - 1; s++) {
        if (s < NI) issue(s, s * 32);
        cp_commit();
    }

    for (int it = 0; it < NI; it++) {
        cp_wait<BT_NSTG - 2>();
        __syncthreads();

        int nxt = it + BT_NSTG - 1;
        if (nxt < NI) issue(nxt % BT_NSTG, nxt * 32);
        cp_commit();

        const int cur = it % BT_NSTG;
        const uint32_t abase = sb + cur * BT_ABUF;
        const uint32_t bbase = sb + BT_BBASE + cur * BT_BBUF;

#pragma unroll
        for (int kk = 0; kk < 32; kk += 16) {
            uint32_t af[4][4];
#pragma unroll
            for (int mt = 0; mt < 4; mt++) {
                uint32_t addr = abase +
                    (wm + mt * 16 + (lane & 15)) * BT_ASTRB +
                    (kk + (lane >> 4) * 8) * 2;
                ldsm_x4(af[mt][0], af[mt][1], af[mt][2], af[mt][3], addr);
            }
            uint32_t bf[4][2];
#pragma unroll
            for (int nt2 = 0; nt2 < 2; nt2++) {
                uint32_t addr = bbase +
                    (kk + (lane & 15)) * BT_BSTRB +
                    (wn + nt2 * 16 + (lane >> 4) * 8) * 2;
                uint32_t r0, r1, r2, r3;
                ldsm_x4_trans(r0, r1, r2, r3, addr);
                bf[nt2 * 2][0] = r0;     bf[nt2 * 2][1] = r1;
                bf[nt2 * 2 + 1][0] = r2; bf[nt2 * 2 + 1][1] = r3;
            }
#pragma unroll
            for (int mt = 0; mt < 4; mt++)
#pragma unroll
                for (int nt = 0; nt < 4; nt++)
                    mma_f16(acc[mt][nt][0], acc[mt][nt][1],
                            acc[mt][nt][2], acc[mt][nt][3],
                            af[mt][0], af[mt][1], af[mt][2], af[mt][3],
                            bf[nt][0], bf[nt][1]);
        }
    }

#pragma unroll
    for (int mt = 0; mt < 4; mt++) {
        int row = m0 + wm + mt * 16 + g;
#pragma unroll
        for (int nt = 0; nt < 4; nt++) {
            int col = n0 + wn + nt * 8 + tg * 2;
            float2 bv = *(const float2*)&bias[col];
            *(float2*)&out[(size_t)row * N + col] =
                make_float2(acc[mt][nt][0] + bv.x, acc[mt][nt][1] + bv.y);
            *(float2*)&out[(size_t)(row + 8) * N + col] =
                make_float2(acc[mt][nt][2] + bv.x, acc[mt][nt][3] + bv.y);
        }
    }
}

// ---------------------------------------------------------------------------
// All-fp16 causal flash attention, 128 queries/CTA, 256 threads = 8 warps;
// warp w owns query rows [w*16, w*16+16). Q is PRE-SCALED by 1/8 upstream.
// K/V double-buffered via cp.async. LPT block order. 2 CTAs/SM.
// ---------------------------------------------------------------------------
#define QSTR 72

__global__ void __launch_bounds__(256, 2) flash_attn_f16(
    const __half* __restrict__ qkv, __half* __restrict__ y)
{
    const int qb  = (gridDim.x - 1) - blockIdx.x;   // LPT: longest CTAs first
    const int bh  = blockIdx.y;
    const int b   = bh >> 4;
    const int h   = bh & 15;
    const int tid = threadIdx.x;
    const int w   = tid >> 5;          // 0..7
    const int lane = tid & 31;
    const int g   = lane >> 2;
    const int tg  = lane & 3;

    __shared__ __align__(16) __half Qs[128][QSTR];
    __shared__ __align__(16) __half Ks[2][64][QSTR];
    __shared__ __align__(16) __half Vs[2][64][QSTR];

    const __half* base = qkv + (size_t)(b * TT) * QKVN + h * HD;
    const int ntiles = 2 * qb + 2;

    const int kr  = tid >> 2;
    const int kc0 = (tid & 3) * 16;
    auto issue_kv = [&](int t, int st) {
        const __half* krow = base + (size_t)(t * 64 + kr) * QKVN + CC;
        uint32_t sk = (uint32_t)__cvta_generic_to_shared(&Ks[st][kr][kc0]);
        uint32_t sv = (uint32_t)__cvta_generic_to_shared(&Vs[st][kr][kc0]);
        cp_async16(sk,      krow + kc0);
        cp_async16(sk + 16, krow + kc0 + 8);
        cp_async16(sv,      krow + CC + kc0);
        cp_async16(sv + 16, krow + CC + kc0 + 8);
    };

    issue_kv(0, 0);
    cp_commit();

    for (int p = tid; p < 128 * 8; p += 256) {
        int r = p >> 3, c = p & 7;
        *(uint4*)&Qs[r][c * 8] =
            *(const uint4*)&base[(size_t)(qb * 128 + r) * QKVN + c * 8];
    }
    __syncthreads();

    uint32_t aq[4][4];
#pragma unroll
    for (int kc = 0; kc < 4; kc++) {
        uint32_t addr = (uint32_t)__cvta_generic_to_shared(
            &Qs[w * 16 + (lane & 15)][kc * 16 + (lane >> 4) * 8]);
        ldsm_x4(aq[kc][0], aq[kc][1], aq[kc][2], aq[kc][3], addr);
    }

    float o[8][4];
#pragma unroll
    for (int nt = 0; nt < 8; nt++)
#pragma unroll
        for (int r = 0; r < 4; r++) o[nt][r] = 0.0f;
    float m0s = -INFINITY, m1s = -INFINITY;
    float l0s = 0.0f, l1s = 0.0f;

    const int q_lo = qb * 128 + w * 16;
    const int q_hi = q_lo + 15;

    for (int t = 0; t < ntiles; t++) {
        const int kt = t * 64;

        cp_wait<0>();
        __syncthreads();
        if (t + 1 < ntiles) issue_kv(t + 1, (t + 1) & 1);
        cp_commit();

        if (kt > q_hi) continue;
        const int st = t & 1;
        const bool need_mask = (kt + 63) > q_lo;

        // ---- S = Q K^T (Q pre-scaled) ----
        float s[8][4];
#pragma unroll
        for (int nt = 0; nt < 8; nt++)
#pragma unroll
            for (int r = 0; r < 4; r++) s[nt][r] = 0.0f;

#pragma unroll
        for (int kc = 0; kc < 4; kc++) {
            uint32_t bf[8][2];
#pragma unroll
            for (int nt2 = 0; nt2 < 4; nt2++) {
                uint32_t addr = (uint32_t)__cvta_generic_to_shared(
                    &Ks[st][nt2 * 16 + (lane & 7) + ((lane >> 4) & 1) * 8]
                          [kc * 16 + ((lane >> 3) & 1) * 8]);
                uint32_t r0, r1, r2, r3;
                ldsm_x4(r0, r1, r2, r3, addr);
                bf[nt2 * 2][0] = r0;     bf[nt2 * 2][1] = r1;
                bf[nt2 * 2 + 1][0] = r2; bf[nt2 * 2 + 1][1] = r3;
            }
#pragma unroll
            for (int nt = 0; nt < 8; nt++)
                mma_f16(s[nt][0], s[nt][1], s[nt][2], s[nt][3],
                        aq[kc][0], aq[kc][1], aq[kc][2], aq[kc][3],
                        bf[nt][0], bf[nt][1]);
        }

        if (need_mask) {
            int rg0 = q_lo + g;
            int rg1 = rg0 + 8;
#pragma unroll
            for (int nt = 0; nt < 8; nt++) {
                int cg = kt + nt * 8 + tg * 2;
                if (cg     > rg0) s[nt][0] = -INFINITY;
                if (cg + 1 > rg0) s[nt][1] = -INFINITY;
                if (cg     > rg1) s[nt][2] = -INFINITY;
                if (cg + 1 > rg1) s[nt][3] = -INFINITY;
            }
        }

        // ---- online softmax ----
        float cm0 = -INFINITY, cm1 = -INFINITY;
#pragma unroll
        for (int nt = 0; nt < 8; nt++) {
            cm0 = fmaxf(cm0, fmaxf(s[nt][0], s[nt][1]));
            cm1 = fmaxf(cm1, fmaxf(s[nt][2], s[nt][3]));
        }
        cm0 = fmaxf(cm0, __shfl_xor_sync(0xffffffffu, cm0, 1));
        cm0 = fmaxf(cm0, __shfl_xor_sync(0xffffffffu, cm0, 2));
        cm1 = fmaxf(cm1, __shfl_xor_sync(0xffffffffu, cm1, 1));
        cm1 = fmaxf(cm1, __shfl_xor_sync(0xffffffffu, cm1, 2));

        float mn0 = fmaxf(m0s, cm0);
        float mn1 = fmaxf(m1s, cm1);
        float corr0 = __expf(m0s - mn0);
        float corr1 = __expf(m1s - mn1);
        m0s = mn0; m1s = mn1;

        uint32_t p01[8], p23[8];
        float ps0 = 0.0f, ps1 = 0.0f;
#pragma unroll
        for (int nt = 0; nt < 8; nt++) {
            float e0 = __expf(s[nt][0] - mn0);
            float e1 = __expf(s[nt][1] - mn0);
            float e2 = __expf(s[nt][2] - mn1);
            float e3 = __expf(s[nt][3] - mn1);
            ps0 += e0 + e1;
            ps1 += e2 + e3;
            half2 h01 = __floats2half2_rn(e0, e1);
            half2 h23 = __floats2half2_rn(e2, e3);
            p01[nt] = *(uint32_t*)&h01;
            p23[nt] = *(uint32_t*)&h23;
        }
        ps0 += __shfl_xor_sync(0xffffffffu, ps0, 1);
        ps0 += __shfl_xor_sync(0xffffffffu, ps0, 2);
        ps1 += __shfl_xor_sync(0xffffffffu, ps1, 1);
        ps1 += __shfl_xor_sync(0xffffffffu, ps1, 2);
        l0s = l0s * corr0 + ps0;
        l1s = l1s * corr1 + ps1;

#pragma unroll
        for (int nt = 0; nt < 8; nt++) {
            o[nt][0] *= corr0; o[nt][1] *= corr0;
            o[nt][2] *= corr1; o[nt][3] *= corr1;
        }

        // ---- O += P V ----
#pragma unroll
        for (int kc = 0; kc < 4; kc++) {
            uint32_t pa0 = p01[2 * kc],     pa1 = p23[2 * kc];
            uint32_t pa2 = p01[2 * kc + 1], pa3 = p23[2 * kc + 1];
#pragma unroll
            for (int np = 0; np < 4; np++) {
                int sub = lane >> 3;
                int key = kc * 16 + (lane & 7) + (sub & 1) * 8;
                int dim = np * 16 + (sub >> 1) * 8;
                uint32_t addr = (uint32_t)__cvta_generic_to_shared(&Vs[st][key][dim]);
                uint32_t b0, b1, b2, b3;
                ldsm_x4_trans(b0, b1, b2, b3, addr);
                mma_f16(o[2*np][0], o[2*np][1], o[2*np][2], o[2*np][3],
                        pa0, pa1, pa2, pa3, b0, b1);
                mma_f16(o[2*np+1][0], o[2*np+1][1], o[2*np+1][2], o[2*np+1][3],
                        pa0, pa1, pa2, pa3, b2, b3);
            }
        }
    }

    // ---- epilogue ----
    __half* ybase = y + (size_t)(b * TT) * CC + h * HD;
    const float inv0 = 1.0f / l0s;
    const float inv1 = 1.0f / l1s;
    const int row0 = q_lo + g;
#pragma unroll
    for (int nt = 0; nt < 8; nt++) {
        int col = nt * 8 + tg * 2;
        *(half2*)&ybase[(size_t)row0 * CC + col] =
            __floats2half2_rn(o[nt][0] * inv0, o[nt][1] * inv0);
        *(half2*)&ybase[(size_t)(row0 + 8) * CC + col] =
            __floats2half2_rn(o[nt][2] * inv1, o[nt][3] * inv1);
    }
}

// ---------------------------------------------------------------------------
// Launch
// ---------------------------------------------------------------------------
extern "C" void kernel_launch(void* const* d_in, const int* in_sizes, int n_in,
                              void* d_out, int out_size)
{
    const float* x     = (const float*)d_in[0];
    const float* w_qkv = (const float*)d_in[1];
    const float* b_qkv = (const float*)d_in[2];
    const float* w_out = (const float*)d_in[3];
    const float* b_out = (const float*)d_in[4];
    float* out = (float*)d_out;

    __half *xh, *wqkvh, *wouth, *qkv, *yb;
    cudaGetSymbolAddress((void**)&xh, g_xh);
    cudaGetSymbolAddress((void**)&wqkvh, g_wqkvh);
    cudaGetSymbolAddress((void**)&wouth, g_wouth);
    cudaGetSymbolAddress((void**)&qkv, g_qkv);
    cudaGetSymbolAddress((void**)&yb, g_y);

    cudaFuncSetAttribute(gemm_f16_qkv_persist,
                         cudaFuncAttributeMaxDynamicSharedMemorySize, HA_SMEM);
    cudaFuncSetAttribute(gemm_f16_bt,
                         cudaFuncAttributeMaxDynamicSharedMemorySize, BT_SMEM);

    // 0) fused fp32 -> fp16 conversions (x, w_qkv, w_out)
    const int n0 = MROWS * CC, n1 = CC * QKVN, n2 = CC * CC;
    f32_to_f16_fused<<<((n0 + n1 + n2) / 8 + 255) / 256, 256>>>(
        x, xh, n0, w_qkv, wqkvh, n1, w_out, wouth, n2);

    // 1) QKV projection (persistent high-occupancy GEMM, Q pre-scaled)
    int dev = 0, nsm = 148;
    cudaGetDevice(&dev);
    cudaDeviceGetAttribute(&nsm, cudaDevAttrMultiProcessorCount, dev);
    int grid = nsm * 3;
    int ntiles = (MROWS / 128) * (QKVN / 64);
    if (grid > ntiles) grid = ntiles;
    gemm_f16_qkv_persist<<<grid, 256, HA_SMEM>>>(
        xh, wqkvh, b_qkv, qkv, MROWS, QKVN, CC);

    // 2) Causal MHA (256-thread, 16 warps/SM) -> fp16 y
    flash_attn_f16<<<dim3(TT / 128, BB * NH), 256>>>(qkv, yb);

    // 3) Output projection (big-tile GEMM) -> fp32 out
    gemm_f16_bt<<<dim3(CC / 128, MROWS / 128), 256, BT_SMEM>>>(
        yb, wouth, b_out, out, MROWS, CC, CC);
}

// round 17
// speedup vs baseline: 1.0230x; 1.0230x over previous
#include <cuda_runtime.h>
#include <cuda_fp16.h>
#include <math.h>
#include <stdint.h>

// Problem constants
#define BB 2
#define TT 2048
#define CC 1024
#define NH 16
#define HD 64
#define MROWS (BB*TT)      // 4096
#define QKVN  (3*CC)       // 3072

// Scratch (allocation-free rule: __device__ globals)
__device__ __half g_xh[MROWS * CC];
__device__ __half g_wqkvh[CC * QKVN];
__device__ __half g_wouth[CC * CC];
__device__ __half g_qkv[MROWS * QKVN];
__device__ __half g_y[MROWS * CC];

// ---------------------------------------------------------------------------
// helpers
// ---------------------------------------------------------------------------
__device__ __forceinline__ void mma_f16(
    float& c0, float& c1, float& c2, float& c3,
    uint32_t a0, uint32_t a1, uint32_t a2, uint32_t a3,
    uint32_t b0, uint32_t b1)
{
    asm volatile(
        "mma.sync.aligned.m16n8k16.row.col.f32.f16.f16.f32 "
        "{%0,%1,%2,%3}, {%4,%5,%6,%7}, {%8,%9}, {%0,%1,%2,%3};"
        : "+f"(c0), "+f"(c1), "+f"(c2), "+f"(c3)
        : "r"(a0), "r"(a1), "r"(a2), "r"(a3), "r"(b0), "r"(b1));
}

__device__ __forceinline__ void ldsm_x4(
    uint32_t& r0, uint32_t& r1, uint32_t& r2, uint32_t& r3, uint32_t addr)
{
    asm volatile(
        "ldmatrix.sync.aligned.m8n8.x4.shared.b16 {%0,%1,%2,%3}, [%4];"
        : "=r"(r0), "=r"(r1), "=r"(r2), "=r"(r3) : "r"(addr));
}

__device__ __forceinline__ void ldsm_x4_trans(
    uint32_t& r0, uint32_t& r1, uint32_t& r2, uint32_t& r3, uint32_t addr)
{
    asm volatile(
        "ldmatrix.sync.aligned.m8n8.x4.trans.shared.b16 {%0,%1,%2,%3}, [%4];"
        : "=r"(r0), "=r"(r1), "=r"(r2), "=r"(r3) : "r"(addr));
}

__device__ __forceinline__ void cp_async16(uint32_t smem, const void* gmem) {
    asm volatile("cp.async.cg.shared.global [%0], [%1], 16;"
                 :: "r"(smem), "l"(gmem));
}
__device__ __forceinline__ void cp_commit() {
    asm volatile("cp.async.commit_group;");
}
template<int N>
__device__ __forceinline__ void cp_wait() {
    asm volatile("cp.async.wait_group %0;" :: "n"(N));
}

// ---------------------------------------------------------------------------
// fused fp32 -> fp16 conversion for three arrays in one launch
// ---------------------------------------------------------------------------
__global__ void f32_to_f16_fused(
    const float* __restrict__ in0, __half* __restrict__ out0, int n0,
    const float* __restrict__ in1, __half* __restrict__ out1, int n1,
    const float* __restrict__ in2, __half* __restrict__ out2, int n2)
{
    int i = (blockIdx.x * blockDim.x + threadIdx.x) * 8;
    const float* in; __half* out;
    if (i < n0)            { in = in0;            out = out0;            }
    else if (i < n0 + n1)  { in = in1 - n0;       out = out1 - n0;       }
    else if (i < n0+n1+n2) { in = in2 - n0 - n1;  out = out2 - n0 - n1;  }
    else return;
    float4 a = *(const float4*)&in[i];
    float4 b = *(const float4*)&in[i + 4];
    half2 h[4];
    h[0] = __floats2half2_rn(a.x, a.y);
    h[1] = __floats2half2_rn(a.z, a.w);
    h[2] = __floats2half2_rn(b.x, b.y);
    h[3] = __floats2half2_rn(b.z, b.w);
    *(uint4*)&out[i] = *(uint4*)&h[0];
}

// ---------------------------------------------------------------------------
// GEMM variant A (high-occupancy, for QKV): CTA 128x64, 8 warps (4m x 2n),
// warp tile 32x32, BK=32, 4-stage cp.async, 3 CTAs/SM.
// Q columns (col < CC) are scaled by 0.125*log2(e) so attention can use
// base-2 softmax (exp2) with no per-score multiply.
// ---------------------------------------------------------------------------
#define QK_SCALE_LOG2E 0.1803368801111204f   // (1/8) * log2(e)

#define HA_ASTRB 80
#define HA_BSTRB 144
#define HA_ABUF (128 * HA_ASTRB)
#define HA_BBUF (32 * HA_BSTRB)
#define HA_NSTG 4
#define HA_BBASE (HA_NSTG * HA_ABUF)
#define HA_SMEM (HA_NSTG * (HA_ABUF + HA_BBUF))   // 59392

__global__ void __launch_bounds__(256, 3) gemm_f16_ho(
    const __half* __restrict__ A, const __half* __restrict__ W,
    const float* __restrict__ bias, __half* __restrict__ out,
    int M, int N, int K)
{
    extern __shared__ __align__(16) char smem[];
    const uint32_t sb = (uint32_t)__cvta_generic_to_shared(smem);

    const int tid  = threadIdx.x;
    const int warp = tid >> 5;
    const int lane = tid & 31;
    const int g    = lane >> 2;
    const int tg   = lane & 3;

    const int wm = (warp & 3) * 32;
    const int wn = (warp >> 2) * 32;
    const int m0 = blockIdx.y * 128;
    const int n0 = blockIdx.x * 64;

    float acc[2][4][4];
#pragma unroll
    for (int i = 0; i < 2; i++)
#pragma unroll
        for (int j = 0; j < 4; j++)
#pragma unroll
            for (int r = 0; r < 4; r++) acc[i][j][r] = 0.0f;

    const int arow = tid >> 1, acol = (tid & 1) * 16;
    const int brow = tid >> 3, bcol = (tid & 7) * 8;

    const int NI = K / 32;

    auto issue = [&](int stage, int k0) {
        uint32_t sa = sb + stage * HA_ABUF + arow * HA_ASTRB + acol * 2;
        const __half* ga = &A[(size_t)(m0 + arow) * K + k0 + acol];
        cp_async16(sa,      ga);
        cp_async16(sa + 16, ga + 8);
        uint32_t sbuf = sb + HA_BBASE + stage * HA_BBUF + brow * HA_BSTRB + bcol * 2;
        const __half* gb = &W[(size_t)(k0 + brow) * N + n0 + bcol];
        cp_async16(sbuf, gb);
    };

#pragma unroll
    for (int s = 0; s < HA_NSTG - 1; s++) {
        if (s < NI) issue(s, s * 32);
        cp_commit();
    }

    for (int it = 0; it < NI; it++) {
        cp_wait<HA_NSTG - 2>();
        __syncthreads();

        int nxt = it + HA_NSTG - 1;
        if (nxt < NI) issue(nxt % HA_NSTG, nxt * 32);
        cp_commit();

        const int cur = it % HA_NSTG;
        const uint32_t abase = sb + cur * HA_ABUF;
        const uint32_t bbase = sb + HA_BBASE + cur * HA_BBUF;

#pragma unroll
        for (int kk = 0; kk < 32; kk += 16) {
            uint32_t af[2][4];
#pragma unroll
            for (int mt = 0; mt < 2; mt++) {
                uint32_t addr = abase +
                    (wm + mt * 16 + (lane & 15)) * HA_ASTRB +
                    (kk + (lane >> 4) * 8) * 2;
                ldsm_x4(af[mt][0], af[mt][1], af[mt][2], af[mt][3], addr);
            }
            uint32_t bf[4][2];
#pragma unroll
            for (int nt2 = 0; nt2 < 2; nt2++) {
                uint32_t addr = bbase +
                    (kk + (lane & 15)) * HA_BSTRB +
                    (wn + nt2 * 16 + (lane >> 4) * 8) * 2;
                uint32_t r0, r1, r2, r3;
                ldsm_x4_trans(r0, r1, r2, r3, addr);
                bf[nt2 * 2][0] = r0;     bf[nt2 * 2][1] = r1;
                bf[nt2 * 2 + 1][0] = r2; bf[nt2 * 2 + 1][1] = r3;
            }
#pragma unroll
            for (int mt = 0; mt < 2; mt++)
#pragma unroll
                for (int nt = 0; nt < 4; nt++)
                    mma_f16(acc[mt][nt][0], acc[mt][nt][1],
                            acc[mt][nt][2], acc[mt][nt][3],
                            af[mt][0], af[mt][1], af[mt][2], af[mt][3],
                            bf[nt][0], bf[nt][1]);
        }
    }

    // Epilogue: Q columns pre-scaled by 0.125*log2(e)
#pragma unroll
    for (int mt = 0; mt < 2; mt++) {
        int row = m0 + wm + mt * 16 + g;
#pragma unroll
        for (int nt = 0; nt < 4; nt++) {
            int col = n0 + wn + nt * 8 + tg * 2;
            float sc = (col < CC) ? QK_SCALE_LOG2E : 1.0f;
            float2 bv = *(const float2*)&bias[col];
            *(half2*)&out[(size_t)row * N + col] =
                __floats2half2_rn((acc[mt][nt][0] + bv.x) * sc,
                                  (acc[mt][nt][1] + bv.y) * sc);
            *(half2*)&out[(size_t)(row + 8) * N + col] =
                __floats2half2_rn((acc[mt][nt][2] + bv.x) * sc,
                                  (acc[mt][nt][3] + bv.y) * sc);
        }
    }
}

// ---------------------------------------------------------------------------
// GEMM variant B (big tile, for out-proj, fp32 out): CTA 128x128, 8 warps
// (2m x 4n), warp tile 64x32, BK=32, 4-stage cp.async.
// ---------------------------------------------------------------------------
#define BT_ASTRB 80
#define BT_BSTRB 272
#define BT_ABUF (128 * BT_ASTRB)
#define BT_BBUF (32 * BT_BSTRB)
#define BT_NSTG 4
#define BT_BBASE (BT_NSTG * BT_ABUF)
#define BT_SMEM (BT_NSTG * (BT_ABUF + BT_BBUF))   // 75776

__global__ void __launch_bounds__(256) gemm_f16_bt(
    const __half* __restrict__ A, const __half* __restrict__ W,
    const float* __restrict__ bias, float* __restrict__ out,
    int M, int N, int K)
{
    extern __shared__ __align__(16) char smem[];
    const uint32_t sb = (uint32_t)__cvta_generic_to_shared(smem);

    const int tid  = threadIdx.x;
    const int warp = tid >> 5;
    const int lane = tid & 31;
    const int g    = lane >> 2;
    const int tg   = lane & 3;

    const int wm = (warp & 1) * 64;
    const int wn = (warp >> 1) * 32;
    const int m0 = blockIdx.y * 128;
    const int n0 = blockIdx.x * 128;

    float acc[4][4][4];
#pragma unroll
    for (int i = 0; i < 4; i++)
#pragma unroll
        for (int j = 0; j < 4; j++)
#pragma unroll
            for (int r = 0; r < 4; r++) acc[i][j][r] = 0.0f;

    const int arow = tid >> 1, acol = (tid & 1) * 16;
    const int brow = tid >> 3, bcol = (tid & 7) * 16;

    const int NI = K / 32;

    auto issue = [&](int stage, int k0) {
        uint32_t sa = sb + stage * BT_ABUF + arow * BT_ASTRB + acol * 2;
        const __half* ga = &A[(size_t)(m0 + arow) * K + k0 + acol];
        cp_async16(sa,      ga);
        cp_async16(sa + 16, ga + 8);
        uint32_t sbuf = sb + BT_BBASE + stage * BT_BBUF + brow * BT_BSTRB + bcol * 2;
        const __half* gb = &W[(size_t)(k0 + brow) * N + n0 + bcol];
        cp_async16(sbuf,      gb);
        cp_async16(sbuf + 16, gb + 8);
    };

#pragma unroll
    for (int s = 0; s < BT_NSTG - 1; s++) {
        if (s < NI) issue(s, s * 32);
        cp_commit();
    }

    for (int it = 0; it < NI; it++) {
        cp_wait<BT_NSTG - 2>();
        __syncthreads();

        int nxt = it + BT_NSTG - 1;
        if (nxt < NI) issue(nxt % BT_NSTG, nxt * 32);
        cp_commit();

        const int cur = it % BT_NSTG;
        const uint32_t abase = sb + cur * BT_ABUF;
        const uint32_t bbase = sb + BT_BBASE + cur * BT_BBUF;

#pragma unroll
        for (int kk = 0; kk < 32; kk += 16) {
            uint32_t af[4][4];
#pragma unroll
            for (int mt = 0; mt < 4; mt++) {
                uint32_t addr = abase +
                    (wm + mt * 16 + (lane & 15)) * BT_ASTRB +
                    (kk + (lane >> 4) * 8) * 2;
                ldsm_x4(af[mt][0], af[mt][1], af[mt][2], af[mt][3], addr);
            }
            uint32_t bf[4][2];
#pragma unroll
            for (int nt2 = 0; nt2 < 2; nt2++) {
                uint32_t addr = bbase +
                    (kk + (lane & 15)) * BT_BSTRB +
                    (wn + nt2 * 16 + (lane >> 4) * 8) * 2;
                uint32_t r0, r1, r2, r3;
                ldsm_x4_trans(r0, r1, r2, r3, addr);
                bf[nt2 * 2][0] = r0;     bf[nt2 * 2][1] = r1;
                bf[nt2 * 2 + 1][0] = r2; bf[nt2 * 2 + 1][1] = r3;
            }
#pragma unroll
            for (int mt = 0; mt < 4; mt++)
#pragma unroll
                for (int nt = 0; nt < 4; nt++)
                    mma_f16(acc[mt][nt][0], acc[mt][nt][1],
                            acc[mt][nt][2], acc[mt][nt][3],
                            af[mt][0], af[mt][1], af[mt][2], af[mt][3],
                            bf[nt][0], bf[nt][1]);
        }
    }

#pragma unroll
    for (int mt = 0; mt < 4; mt++) {
        int row = m0 + wm + mt * 16 + g;
#pragma unroll
        for (int nt = 0; nt < 4; nt++) {
            int col = n0 + wn + nt * 8 + tg * 2;
            float2 bv = *(const float2*)&bias[col];
            *(float2*)&out[(size_t)row * N + col] =
                make_float2(acc[mt][nt][0] + bv.x, acc[mt][nt][1] + bv.y);
            *(float2*)&out[(size_t)(row + 8) * N + col] =
                make_float2(acc[mt][nt][2] + bv.x, acc[mt][nt][3] + bv.y);
        }
    }
}

// ---------------------------------------------------------------------------
// All-fp16 causal flash attention, 128 queries/CTA, 256 threads = 8 warps;
// warp w owns query rows [w*16, w*16+16). Q PRE-SCALED by 0.125*log2e, so
// softmax is base-2 (exp2). Fully-masked nt/kc chunks of the diagonal tile
// are skipped (warp-uniform predicates). K/V double-buffered via cp.async.
// LPT block order. 2 CTAs/SM.
// ---------------------------------------------------------------------------
#define QSTR 72

__global__ void __launch_bounds__(256, 2) flash_attn_f16(
    const __half* __restrict__ qkv, __half* __restrict__ y)
{
    const int qb  = (gridDim.x - 1) - blockIdx.x;   // LPT: longest CTAs first
    const int bh  = blockIdx.y;
    const int b   = bh >> 4;
    const int h   = bh & 15;
    const int tid = threadIdx.x;
    const int w   = tid >> 5;          // 0..7
    const int lane = tid & 31;
    const int g   = lane >> 2;
    const int tg  = lane & 3;

    __shared__ __align__(16) __half Qs[128][QSTR];
    __shared__ __align__(16) __half Ks[2][64][QSTR];
    __shared__ __align__(16) __half Vs[2][64][QSTR];

    const __half* base = qkv + (size_t)(b * TT) * QKVN + h * HD;
    const int ntiles = 2 * qb + 2;

    const int kr  = tid >> 2;
    const int kc0 = (tid & 3) * 16;
    auto issue_kv = [&](int t, int st) {
        const __half* krow = base + (size_t)(t * 64 + kr) * QKVN + CC;
        uint32_t sk = (uint32_t)__cvta_generic_to_shared(&Ks[st][kr][kc0]);
        uint32_t sv = (uint32_t)__cvta_generic_to_shared(&Vs[st][kr][kc0]);
        cp_async16(sk,      krow + kc0);
        cp_async16(sk + 16, krow + kc0 + 8);
        cp_async16(sv,      krow + CC + kc0);
        cp_async16(sv + 16, krow + CC + kc0 + 8);
    };

    issue_kv(0, 0);
    cp_commit();

    for (int p = tid; p < 128 * 8; p += 256) {
        int r = p >> 3, c = p & 7;
        *(uint4*)&Qs[r][c * 8] =
            *(const uint4*)&base[(size_t)(qb * 128 + r) * QKVN + c * 8];
    }
    __syncthreads();

    uint32_t aq[4][4];
#pragma unroll
    for (int kc = 0; kc < 4; kc++) {
        uint32_t addr = (uint32_t)__cvta_generic_to_shared(
            &Qs[w * 16 + (lane & 15)][kc * 16 + (lane >> 4) * 8]);
        ldsm_x4(aq[kc][0], aq[kc][1], aq[kc][2], aq[kc][3], addr);
    }

    float o[8][4];
#pragma unroll
    for (int nt = 0; nt < 8; nt++)
#pragma unroll
        for (int r = 0; r < 4; r++) o[nt][r] = 0.0f;
    float m0s = -INFINITY, m1s = -INFINITY;
    float l0s = 0.0f, l1s = 0.0f;

    const int q_lo = qb * 128 + w * 16;
    const int q_hi = q_lo + 15;

    for (int t = 0; t < ntiles; t++) {
        const int kt = t * 64;

        cp_wait<0>();
        __syncthreads();
        if (t + 1 < ntiles) issue_kv(t + 1, (t + 1) & 1);
        cp_commit();

        if (kt > q_hi) continue;          // fully masked for this warp
        const int st = t & 1;
        const bool need_mask = (kt + 63) > q_lo;

        // ---- S = Q K^T (Q pre-scaled, log2 units) ----
        float s[8][4];
#pragma unroll
        for (int nt = 0; nt < 8; nt++)
#pragma unroll
            for (int r = 0; r < 4; r++) s[nt][r] = 0.0f;

#pragma unroll
        for (int kc = 0; kc < 4; kc++) {
            uint32_t bf[8][2];
#pragma unroll
            for (int nt2 = 0; nt2 < 4; nt2++) {
                if (kt + nt2 * 16 > q_hi) continue;   // fully masked 16-key chunk
                uint32_t addr = (uint32_t)__cvta_generic_to_shared(
                    &Ks[st][nt2 * 16 + (lane & 7) + ((lane >> 4) & 1) * 8]
                          [kc * 16 + ((lane >> 3) & 1) * 8]);
                uint32_t r0, r1, r2, r3;
                ldsm_x4(r0, r1, r2, r3, addr);
                bf[nt2 * 2][0] = r0;     bf[nt2 * 2][1] = r1;
                bf[nt2 * 2 + 1][0] = r2; bf[nt2 * 2 + 1][1] = r3;
            }
#pragma unroll
            for (int nt = 0; nt < 8; nt++) {
                if (kt + nt * 8 > q_hi) continue;     // fully masked 8-key chunk
                mma_f16(s[nt][0], s[nt][1], s[nt][2], s[nt][3],
                        aq[kc][0], aq[kc][1], aq[kc][2], aq[kc][3],
                        bf[nt][0], bf[nt][1]);
            }
        }

        if (need_mask) {
            int rg0 = q_lo + g;
            int rg1 = rg0 + 8;
#pragma unroll
            for (int nt = 0; nt < 8; nt++) {
                int cg = kt + nt * 8 + tg * 2;
                if (cg     > rg0) s[nt][0] = -INFINITY;
                if (cg + 1 > rg0) s[nt][1] = -INFINITY;
                if (cg     > rg1) s[nt][2] = -INFINITY;
                if (cg + 1 > rg1) s[nt][3] = -INFINITY;
            }
        }

        // ---- online softmax (base 2) ----
        float cm0 = -INFINITY, cm1 = -INFINITY;
#pragma unroll
        for (int nt = 0; nt < 8; nt++) {
            cm0 = fmaxf(cm0, fmaxf(s[nt][0], s[nt][1]));
            cm1 = fmaxf(cm1, fmaxf(s[nt][2], s[nt][3]));
        }
        cm0 = fmaxf(cm0, __shfl_xor_sync(0xffffffffu, cm0, 1));
        cm0 = fmaxf(cm0, __shfl_xor_sync(0xffffffffu, cm0, 2));
        cm1 = fmaxf(cm1, __shfl_xor_sync(0xffffffffu, cm1, 1));
        cm1 = fmaxf(cm1, __shfl_xor_sync(0xffffffffu, cm1, 2));

        float mn0 = fmaxf(m0s, cm0);
        float mn1 = fmaxf(m1s, cm1);
        float corr0 = exp2f(m0s - mn0);
        float corr1 = exp2f(m1s - mn1);
        m0s = mn0; m1s = mn1;

        uint32_t p01[8], p23[8];
        float ps0 = 0.0f, ps1 = 0.0f;
#pragma unroll
        for (int nt = 0; nt < 8; nt++) {
            float e0 = exp2f(s[nt][0] - mn0);
            float e1 = exp2f(s[nt][1] - mn0);
            float e2 = exp2f(s[nt][2] - mn1);
            float e3 = exp2f(s[nt][3] - mn1);
            ps0 += e0 + e1;
            ps1 += e2 + e3;
            half2 h01 = __floats2half2_rn(e0, e1);
            half2 h23 = __floats2half2_rn(e2, e3);
            p01[nt] = *(uint32_t*)&h01;
            p23[nt] = *(uint32_t*)&h23;
        }
        ps0 += __shfl_xor_sync(0xffffffffu, ps0, 1);
        ps0 += __shfl_xor_sync(0xffffffffu, ps0, 2);
        ps1 += __shfl_xor_sync(0xffffffffu, ps1, 1);
        ps1 += __shfl_xor_sync(0xffffffffu, ps1, 2);
        l0s = l0s * corr0 + ps0;
        l1s = l1s * corr1 + ps1;

#pragma unroll
        for (int nt = 0; nt < 8; nt++) {
            o[nt][0] *= corr0; o[nt][1] *= corr0;
            o[nt][2] *= corr1; o[nt][3] *= corr1;
        }

        // ---- O += P V (skip fully-masked 16-key chunks) ----
#pragma unroll
        for (int kc = 0; kc < 4; kc++) {
            if (kt + kc * 16 > q_hi) continue;        // p == 0 for these keys
            uint32_t pa0 = p01[2 * kc],     pa1 = p23[2 * kc];
            uint32_t pa2 = p01[2 * kc + 1], pa3 = p23[2 * kc + 1];
#pragma unroll
            for (int np = 0; np < 4; np++) {
                int sub = lane >> 3;
                int key = kc * 16 + (lane & 7) + (sub & 1) * 8;
                int dim = np * 16 + (sub >> 1) * 8;
                uint32_t addr = (uint32_t)__cvta_generic_to_shared(&Vs[st][key][dim]);
                uint32_t b0, b1, b2, b3;
                ldsm_x4_trans(b0, b1, b2, b3, addr);
                mma_f16(o[2*np][0], o[2*np][1], o[2*np][2], o[2*np][3],
                        pa0, pa1, pa2, pa3, b0, b1);
                mma_f16(o[2*np+1][0], o[2*np+1][1], o[2*np+1][2], o[2*np+1][3],
                        pa0, pa1, pa2, pa3, b2, b3);
            }
        }
    }

    // ---- epilogue ----
    __half* ybase = y + (size_t)(b * TT) * CC + h * HD;
    const float inv0 = 1.0f / l0s;
    const float inv1 = 1.0f / l1s;
    const int row0 = q_lo + g;
#pragma unroll
    for (int nt = 0; nt < 8; nt++) {
        int col = nt * 8 + tg * 2;
        *(half2*)&ybase[(size_t)row0 * CC + col] =
            __floats2half2_rn(o[nt][0] * inv0, o[nt][1] * inv0);
        *(half2*)&ybase[(size_t)(row0 + 8) * CC + col] =
            __floats2half2_rn(o[nt][2] * inv1, o[nt][3] * inv1);
    }
}

// ---------------------------------------------------------------------------
// Launch
// ---------------------------------------------------------------------------
extern "C" void kernel_launch(void* const* d_in, const int* in_sizes, int n_in,
                              void* d_out, int out_size)
{
    const float* x     = (const float*)d_in[0];
    const float* w_qkv = (const float*)d_in[1];
    const float* b_qkv = (const float*)d_in[2];
    const float* w_out = (const float*)d_in[3];
    const float* b_out = (const float*)d_in[4];
    float* out = (float*)d_out;

    __half *xh, *wqkvh, *wouth, *qkv, *yb;
    cudaGetSymbolAddress((void**)&xh, g_xh);
    cudaGetSymbolAddress((void**)&wqkvh, g_wqkvh);
    cudaGetSymbolAddress((void**)&wouth, g_wouth);
    cudaGetSymbolAddress((void**)&qkv, g_qkv);
    cudaGetSymbolAddress((void**)&yb, g_y);

    cudaFuncSetAttribute(gemm_f16_ho,
                         cudaFuncAttributeMaxDynamicSharedMemorySize, HA_SMEM);
    cudaFuncSetAttribute(gemm_f16_bt,
                         cudaFuncAttributeMaxDynamicSharedMemorySize, BT_SMEM);

    // 0) fused fp32 -> fp16 conversions (x, w_qkv, w_out)
    const int n0 = MROWS * CC, n1 = CC * QKVN, n2 = CC * CC;
    f32_to_f16_fused<<<((n0 + n1 + n2) / 8 + 255) / 256, 256>>>(
        x, xh, n0, w_qkv, wqkvh, n1, w_out, wouth, n2);

    // 1) QKV projection (high-occupancy GEMM, Q pre-scaled for base-2 softmax)
    gemm_f16_ho<<<dim3(QKVN / 64, MROWS / 128), 256, HA_SMEM>>>(
        xh, wqkvh, b_qkv, qkv, MROWS, QKVN, CC);

    // 2) Causal MHA (256-thread, base-2 softmax, masked-chunk skipping)
    flash_attn_f16<<<dim3(TT / 128, BB * NH), 256>>>(qkv, yb);

    // 3) Output projection (big-tile GEMM) -> fp32 out
    gemm_f16_bt<<<dim3(CC / 128, MROWS / 128), 256, BT_SMEM>>>(
        yb, wouth, b_out, out, MROWS, CC, CC);
}